// round 10
// baseline (speedup 1.0000x reference)
#include <cuda_runtime.h>
#include <math.h>

// Problem constants
#define BB   4
#define CIN  128
#define HH   96
#define WWW  96
#define OO   128
#define PP   9216      // H*W
#define PT   64        // pixel tile per block
#define NPT  144       // PP / PT
#define CC   32        // c-rows per chunk
#define NCH  36        // 9*128 / CC

typedef unsigned long long ull;

// Scratch (device globals — no allocation allowed)
__device__ float g_off [BB * 18 * PP];     // (b, 2k+d, p)
__device__ float g_mask[BB * 9  * PP];     // (b, k, p) — sigmoid applied
__device__ float g_wt  [9 * CIN * OO];     // (k, c, o)  transposed deform_w
__device__ float g_owt [9 * CIN * 32];     // (k, c, slot) transposed offset/mask w

// ---- packed fp32x2 helpers (Blackwell FFMA2) --------------------------------
__device__ __forceinline__ void fma2(ull& d, ull a, ull b) {
    asm("fma.rn.f32x2 %0, %1, %2, %0;" : "+l"(d) : "l"(a), "l"(b));
}
__device__ __forceinline__ float2 unpack2(ull v) {
    unsigned lo, hi;
    asm("mov.b64 {%0, %1}, %2;" : "=r"(lo), "=r"(hi) : "l"(v));
    return make_float2(__uint_as_float(lo), __uint_as_float(hi));
}
// STS that writes two lane-duplicated f32x2 pairs: {a,a,b,b} — dup is free.
__device__ __forceinline__ void sts_dup2(void* smem, float a, float b) {
    unsigned s = (unsigned)__cvta_generic_to_shared(smem);
    asm volatile("st.shared.v4.b32 [%0], {%1, %1, %2, %2};"
                 :: "r"(s), "r"(__float_as_uint(a)), "r"(__float_as_uint(b)));
}

// ---------------------------------------------------------------------------
// Kernel 0: one-time weight transposes so GEMM staging is coalesced.
// ---------------------------------------------------------------------------
__global__ __launch_bounds__(256) void transpose_w_kernel(
    const float* __restrict__ dw,
    const float* __restrict__ ow,
    const float* __restrict__ mw)
{
    int i = blockIdx.x * 256 + threadIdx.x;
    if (i < 9 * CIN * OO) {
        int o = i & 127, c = (i >> 7) & 127, k = i >> 14;
        g_wt[i] = dw[(o * CIN + c) * 9 + k];
    }
    if (i < 9 * CIN * 32) {
        int s = i & 31, c = (i >> 5) & 127, k = i >> 12;
        float w = 0.f;
        if (s < 18)      w = ow[(s * CIN + c) * 9 + k];
        else if (s < 27) w = mw[((s - 18) * CIN + c) * 9 + k];
        g_owt[i] = w;
    }
}

// ---------------------------------------------------------------------------
// Kernel 1: offset conv (18ch) + mask conv (9ch, sigmoid), fused implicit GEMM
//   Y[32slots, 64p] = W[32,1152] @ Im2col[1152,64]
// 36 chunks of 32 c-rows; smem weights are lane-duplicated f32x2 pairs.
// ---------------------------------------------------------------------------
__global__ __launch_bounds__(256, 2) void offmask_kernel(
    const float* __restrict__ x2,
    const float* __restrict__ offset_b, const float* __restrict__ mask_b)
{
    __shared__ __align__(16) ull   wsm2[CC][32];   // 8KB, dup'd pairs
    __shared__ __align__(16) float vsm [CC][64];   // 8KB

    const int tid = threadIdx.x;
    const int b  = blockIdx.y;
    const int p0 = blockIdx.x * PT;
    const int tx = tid & 15;
    const int ty = tid >> 4;
    const int vpl = tid & 63;
    const int vho = (p0 + vpl) / WWW, vwo = (p0 + vpl) % WWW;

    ull acc2[2][2] = {{0ull,0ull},{0ull,0ull}};

    for (int ch = 0; ch < NCH; ch++) {
        const int k  = ch >> 2;
        const int c0 = (ch & 3) * CC;
        const int ky = k / 3, kx = k % 3;
        __syncthreads();
        // stage weights: 1024 floats -> dup'd pairs. 1 float4 per thread.
        {
            int cc = tid >> 3, s4 = (tid & 7) * 4;
            float4 w = *(const float4*)&g_owt[(k * CIN + c0 + cc) * 32 + s4];
            sts_dup2(&wsm2[cc][s4],     w.x, w.y);
            sts_dup2(&wsm2[cc][s4 + 2], w.z, w.w);
        }
        // stage im2col values: 2048 floats, 8 per thread
        {
            int y = vho - 1 + ky, x = vwo - 1 + kx;
            bool ok = (unsigned)y < (unsigned)HH && (unsigned)x < (unsigned)WWW;
            int base = (b * CIN + c0) * PP + y * WWW + x;
#pragma unroll
            for (int r = 0; r < 8; r++) {
                int cc = (tid >> 6) + r * 4;
                float v = ok ? x2[base + cc * PP] : 0.f;
                vsm[cc][vpl] = v;
            }
        }
        __syncthreads();
#pragma unroll
        for (int cc = 0; cc < CC; cc++) {
            ulonglong2 w = *(const ulonglong2*)&wsm2[cc][ty * 2];
            ulonglong2 v = *(const ulonglong2*)&vsm[cc][tx * 4];
            fma2(acc2[0][0], w.x, v.x);
            fma2(acc2[0][1], w.x, v.y);
            fma2(acc2[1][0], w.y, v.x);
            fma2(acc2[1][1], w.y, v.y);
        }
    }

    // epilogue: bias; sigmoid for mask channels
#pragma unroll
    for (int i = 0; i < 2; i++) {
        int oc = ty * 2 + i;
        float a[4];
        float2 lo = unpack2(acc2[i][0]);
        float2 hi = unpack2(acc2[i][1]);
        a[0] = lo.x; a[1] = lo.y; a[2] = hi.x; a[3] = hi.y;
#pragma unroll
        for (int j = 0; j < 4; j++) {
            int p = p0 + tx * 4 + j;
            if (oc < 18) {
                g_off[(b * 18 + oc) * PP + p] = a[j] + offset_b[oc];
            } else if (oc < 27) {
                float sg = a[j] + mask_b[oc - 18];
                g_mask[(b * 9 + (oc - 18)) * PP + p] = 1.f / (1.f + expf(-sg));
            }
        }
    }
}

// ---------------------------------------------------------------------------
// Kernel 2: modulated deformable conv v2 as implicit GEMM:
//   out[128o, 64p] = W[128, 1152] @ V[1152, 64]
// 36 chunks of 32 c-rows. smem weights are lane-duplicated f32x2 pairs
// (dup free in STS). Math loop: pure LDS.128 + FFMA2, zero packing ops.
// ---------------------------------------------------------------------------
__global__ __launch_bounds__(256, 2) void deform_kernel(
    const float* __restrict__ x,
    const float* __restrict__ deform_b,
    float* __restrict__ out)
{
    __shared__ __align__(16) int   sidx[9][64][4];   // 9KB
    __shared__ __align__(16) float swt [9][64][4];   // 9KB
    __shared__ __align__(16) ull   wsm2[CC][128];    // 32KB, dup'd pairs
    __shared__ __align__(16) float vsm [CC][64];     // 8KB

    const int tid = threadIdx.x;
    const int b  = blockIdx.y;
    const int p0 = blockIdx.x * PT;
    const int tx = tid & 15;        // -> 4 pixels
    const int ty = tid >> 4;        // -> 8 out channels
    const int vpl = tid & 63;

    // ---- precompute bilinear corner metadata for 64 pixels x 9 taps ----
    for (int idx = tid; idx < 9 * 64; idx += 256) {
        int k = idx >> 6, pl = idx & 63;
        int p  = p0 + pl;
        int ho = p / WWW, wo = p % WWW;
        int ky = k / 3, kx = k % 3;
        float dy = g_off[(b * 18 + 2 * k    ) * PP + p];
        float dx = g_off[(b * 18 + 2 * k + 1) * PP + p];
        float m  = g_mask[(b * 9 + k) * PP + p];
        float py = (float)(ho - 1 + ky) + dy;
        float px = (float)(wo - 1 + kx) + dx;
        float fy = floorf(py), fx = floorf(px);
        int y0 = (int)fy, x0 = (int)fx;
        int y1 = y0 + 1,  x1 = x0 + 1;
        float ly = py - fy, lx = px - fx;
        float hy = 1.f - ly, hx = 1.f - lx;
        bool vy0 = (unsigned)y0 < (unsigned)HH, vy1 = (unsigned)y1 < (unsigned)HH;
        bool vx0 = (unsigned)x0 < (unsigned)WWW, vx1 = (unsigned)x1 < (unsigned)WWW;
        bool v00 = vy0 && vx0, v01 = vy0 && vx1, v10 = vy1 && vx0, v11 = vy1 && vx1;
        sidx[k][pl][0] = v00 ? (y0 * WWW + x0) : 0;
        sidx[k][pl][1] = v01 ? (y0 * WWW + x1) : 0;
        sidx[k][pl][2] = v10 ? (y1 * WWW + x0) : 0;
        sidx[k][pl][3] = v11 ? (y1 * WWW + x1) : 0;
        swt[k][pl][0] = v00 ? hy * hx * m : 0.f;
        swt[k][pl][1] = v01 ? hy * lx * m : 0.f;
        swt[k][pl][2] = v10 ? ly * hx * m : 0.f;
        swt[k][pl][3] = v11 ? ly * lx * m : 0.f;
    }

    ull acc2[8][2];
#pragma unroll
    for (int i = 0; i < 8; i++) { acc2[i][0] = 0ull; acc2[i][1] = 0ull; }

    for (int ch = 0; ch < NCH; ch++) {
        const int k  = ch >> 2;
        const int c0 = (ch & 3) * CC;
        __syncthreads();
        // stage weights: 4096 floats -> dup'd pairs. 4 float4 per thread.
#pragma unroll
        for (int r = 0; r < 4; r++) {
            int idx = tid + r * 256;            // 0..1023 float4 slots
            int cc = idx >> 5, o4 = (idx & 31) * 4;
            float4 w = *(const float4*)&g_wt[(k * CIN + c0 + cc) * OO + o4];
            sts_dup2(&wsm2[cc][o4],     w.x, w.y);
            sts_dup2(&wsm2[cc][o4 + 2], w.z, w.w);
        }
        // stage sampled values: 2048 floats, 8 per thread (same pixel, 8 c's)
        {
            int4   id = *(const int4*)  &sidx[k][vpl][0];
            float4 wq = *(const float4*)&swt [k][vpl][0];
            const float* base0 = x + (size_t)(b * CIN + c0) * PP;
#pragma unroll
            for (int r = 0; r < 8; r++) {
                int cc = (tid >> 6) + r * 4;
                const float* base = base0 + (size_t)cc * PP;
                float v = wq.x * base[id.x];
                v = fmaf(wq.y, base[id.y], v);
                v = fmaf(wq.z, base[id.z], v);
                v = fmaf(wq.w, base[id.w], v);
                vsm[cc][vpl] = v;
            }
        }
        __syncthreads();
        // 32 rank-1 updates of 8oc x 4p per thread, pure LDS + FFMA2
#pragma unroll
        for (int cc = 0; cc < CC; cc++) {
            ulonglong2 w01 = *(const ulonglong2*)&wsm2[cc][ty * 8];
            ulonglong2 w23 = *(const ulonglong2*)&wsm2[cc][ty * 8 + 2];
            ulonglong2 w45 = *(const ulonglong2*)&wsm2[cc][ty * 8 + 4];
            ulonglong2 w67 = *(const ulonglong2*)&wsm2[cc][ty * 8 + 6];
            ulonglong2 v   = *(const ulonglong2*)&vsm [cc][tx * 4];
            fma2(acc2[0][0], w01.x, v.x);  fma2(acc2[0][1], w01.x, v.y);
            fma2(acc2[1][0], w01.y, v.x);  fma2(acc2[1][1], w01.y, v.y);
            fma2(acc2[2][0], w23.x, v.x);  fma2(acc2[2][1], w23.x, v.y);
            fma2(acc2[3][0], w23.y, v.x);  fma2(acc2[3][1], w23.y, v.y);
            fma2(acc2[4][0], w45.x, v.x);  fma2(acc2[4][1], w45.x, v.y);
            fma2(acc2[5][0], w45.y, v.x);  fma2(acc2[5][1], w45.y, v.y);
            fma2(acc2[6][0], w67.x, v.x);  fma2(acc2[6][1], w67.x, v.y);
            fma2(acc2[7][0], w67.y, v.x);  fma2(acc2[7][1], w67.y, v.y);
        }
    }

    // epilogue: bias + vectorized store
#pragma unroll
    for (int i = 0; i < 8; i++) {
        int oc = ty * 8 + i;
        float bias = deform_b[oc];
        float2 lo = unpack2(acc2[i][0]);
        float2 hi = unpack2(acc2[i][1]);
        float4 o;
        o.x = lo.x + bias;
        o.y = lo.y + bias;
        o.z = hi.x + bias;
        o.w = hi.y + bias;
        *(float4*)&out[(size_t)(b * OO + oc) * PP + p0 + tx * 4] = o;
    }
}

// ---------------------------------------------------------------------------
extern "C" void kernel_launch(void* const* d_in, const int* in_sizes, int n_in,
                              void* d_out, int out_size)
{
    const float* x        = (const float*)d_in[0];
    const float* x2       = (const float*)d_in[1];
    const float* offset_w = (const float*)d_in[2];
    const float* offset_b = (const float*)d_in[3];
    const float* mask_w   = (const float*)d_in[4];
    const float* mask_b   = (const float*)d_in[5];
    const float* deform_w = (const float*)d_in[6];
    const float* deform_b = (const float*)d_in[7];
    float* out = (float*)d_out;

    transpose_w_kernel<<<(9 * CIN * OO + 255) / 256, 256>>>(deform_w, offset_w, mask_w);
    dim3 grid(NPT, BB);
    offmask_kernel<<<grid, 256>>>(x2, offset_b, mask_b);
    deform_kernel<<<grid, 256>>>(x, deform_b, out);
}